// round 2
// baseline (speedup 1.0000x reference)
#include <cuda_runtime.h>
#include <cuda_bf16.h>

// Problem constants (fixed shapes for this problem)
#define B_  8
#define H_  8
#define N_  512
#define K_  16
#define BN  (B_*N_)          // 4096
#define RPB 4                // rows (i) per block in main kernel

__device__ float g_Om[BN * K_ * K_];   // per-(b,n) rotation, row-major 16x16
__device__ float g_V[BN * K_];         // v = Om^T mu

// ---------------------------------------------------------------------------
// Kernel 1: per (b,n) matrix exponential of phi_alg = sum_g phi_g * G_g,
// via scaling (2^-5) + Taylor-8 (Horner) + 5 squarings. Also v = Om^T mu.
// One block of 256 threads per matrix; thread t owns element (t>>4, t&15).
// ---------------------------------------------------------------------------
__global__ __launch_bounds__(256)
void expm_v_kernel(const float* __restrict__ mu,
                   const float* __restrict__ phi,
                   const float* __restrict__ gen) {
    __shared__ float Gs[3 * 256];
    __shared__ float As[256];
    __shared__ float Buf0[256], Buf1[256];
    __shared__ float musm[16];

    int bn = blockIdx.x;
    int t  = threadIdx.x;
    int r  = t >> 4, c = t & 15;

    for (int idx = t; idx < 768; idx += 256) Gs[idx] = gen[idx];
    if (t < 16) musm[t] = mu[bn * 16 + t];
    __syncthreads();

    float p0 = phi[bn * 3 + 0], p1 = phi[bn * 3 + 1], p2 = phi[bn * 3 + 2];
    const float SCALE = 1.0f / 32.0f;   // 2^-5
    float a = (p0 * Gs[t] + p1 * Gs[256 + t] + p2 * Gs[512 + t]) * SCALE;
    As[t] = a;

    float* cur = Buf0;
    float* nxt = Buf1;
    const int M = 8;
    cur[t] = (r == c ? 1.0f : 0.0f) + a * (1.0f / (float)M);
    __syncthreads();

    // Horner: R = I + (A/k) * R, k = M-1 .. 1
    #pragma unroll
    for (int k = M - 1; k >= 1; --k) {
        float acc = 0.0f;
        #pragma unroll
        for (int p = 0; p < 16; ++p) acc += As[r * 16 + p] * cur[p * 16 + c];
        nxt[t] = (r == c ? 1.0f : 0.0f) + acc * (1.0f / (float)k);
        __syncthreads();
        float* tmp = cur; cur = nxt; nxt = tmp;
    }
    // 5 squarings
    #pragma unroll
    for (int sq = 0; sq < 5; ++sq) {
        float acc = 0.0f;
        #pragma unroll
        for (int p = 0; p < 16; ++p) acc += cur[r * 16 + p] * cur[p * 16 + c];
        nxt[t] = acc;
        __syncthreads();
        float* tmp = cur; cur = nxt; nxt = tmp;
    }

    g_Om[(size_t)bn * 256 + t] = cur[t];

    if (t < 16) {  // v = Om^T mu  (v_c = sum_r Om[r][c] mu[r])
        float acc = 0.0f;
        #pragma unroll
        for (int rr = 0; rr < 16; ++rr) acc += cur[rr * 16 + t] * musm[rr];
        g_V[bn * 16 + t] = acc;
    }
}

// ---------------------------------------------------------------------------
// Kernel 2: per (b,i) row pass over j. Fuses beta head-average, KL weights,
// the four row-reductions, rotation by Om_i, and the mu update.
// Block = 256 threads handles RPB consecutive i of one batch; V[b] cached in
// smem with stride-17 padding (conflict-free).
// ---------------------------------------------------------------------------
__global__ __launch_bounds__(256)
void vffn_main_kernel(const float* __restrict__ beta,
                      const float* __restrict__ mu,
                      const float* __restrict__ mu_prior,
                      const float* __restrict__ lr_ptr,
                      float* __restrict__ out) {
    __shared__ float Vs[N_ * 17];
    __shared__ float qs[N_];
    __shared__ float red[8][34];
    __shared__ float fin[34];
    __shared__ float rv[16];

    const float ALPHA   = 0.001f;
    const float INV_TAU = 1.0f;       // 1/tau
    const float INV_TK  = 1.0f;       // 1/(tau*kappa)

    int t    = threadIdx.x;
    int lane = t & 31, warp = t >> 5;
    int blk  = blockIdx.x;
    int b    = blk / (N_ / RPB);
    int i0   = (blk % (N_ / RPB)) * RPB;
    float lr = *lr_ptr;

    // Load V[b] into padded smem
    for (int idx = t; idx < N_ * K_; idx += 256) {
        int j = idx >> 4, k = idx & 15;
        Vs[j * 17 + k] = g_V[(size_t)b * N_ * K_ + idx];
    }
    __syncthreads();
    for (int j = t; j < N_; j += 256) {
        float q = 0.0f;
        #pragma unroll
        for (int k = 0; k < 16; ++k) { float v = Vs[j * 17 + k]; q += v * v; }
        qs[j] = q;
    }
    __syncthreads();

    for (int ii = 0; ii < RPB; ++ii) {
        int i  = i0 + ii;
        int bn = b * N_ + i;

        float vi[16];
        #pragma unroll
        for (int k = 0; k < 16; ++k) vi[k] = Vs[i * 17 + k];  // broadcast
        float qi = qs[i];

        float S0 = 0.0f, sac = 0.0f;
        float Sv[16], Tv[16];
        #pragma unroll
        for (int k = 0; k < 16; ++k) { Sv[k] = 0.0f; Tv[k] = 0.0f; }

        const float* bb = beta + (size_t)b * H_ * N_ * N_ + (size_t)i * N_;

        // Batch all 16 independent global loads first (MLP for HBM saturation)
        float bv[2][8];
        #pragma unroll
        for (int dj = 0; dj < 2; ++dj) {
            int j = t + dj * 256;
            #pragma unroll
            for (int h = 0; h < 8; ++h)
                bv[dj][h] = bb[(size_t)h * N_ * N_ + j];
        }

        #pragma unroll
        for (int dj = 0; dj < 2; ++dj) {
            int j = t + dj * 256;
            float csum = 0.0f;
            #pragma unroll
            for (int h = 0; h < 8; ++h) csum += bv[dj][h];
            float cbeta = csum * (1.0f / (float)H_);

            float dot = 0.0f;
            float vj[16];
            #pragma unroll
            for (int k = 0; k < 16; ++k) {
                vj[k] = Vs[j * 17 + k];
                dot += vi[k] * vj[k];
            }
            float kl = (0.5f * (qi + qs[j]) - dot) * INV_TAU;
            float w  = cbeta * kl;
            S0  += cbeta;
            sac += w;
            #pragma unroll
            for (int k = 0; k < 16; ++k) {
                Sv[k] += cbeta * vj[k];
                Tv[k] += w * vj[k];
            }
        }

        // Warp-level reduction of the 34 partials
        #pragma unroll
        for (int off = 16; off > 0; off >>= 1) {
            S0  += __shfl_xor_sync(0xffffffffu, S0,  off);
            sac += __shfl_xor_sync(0xffffffffu, sac, off);
            #pragma unroll
            for (int k = 0; k < 16; ++k) {
                Sv[k] += __shfl_xor_sync(0xffffffffu, Sv[k], off);
                Tv[k] += __shfl_xor_sync(0xffffffffu, Tv[k], off);
            }
        }
        if (lane == 0) {
            red[warp][0] = S0; red[warp][1] = sac;
            #pragma unroll
            for (int k = 0; k < 16; ++k) {
                red[warp][2 + k]  = Sv[k];
                red[warp][18 + k] = Tv[k];
            }
        }
        __syncthreads();
        if (t < 34) {
            float a = 0.0f;
            #pragma unroll
            for (int w8 = 0; w8 < 8; ++w8) a += red[w8][t];
            fin[t] = a;
        }
        __syncthreads();

        if (t < 16) {
            float S0f = fin[0], sf = fin[1];
            float Svk = fin[2 + t], Tvk = fin[18 + t];
            float vik = vi[t];
            float r1 = (S0f * vik - Svk) * INV_TAU;                        // grad1 (pre-rotation)
            float r2 = (sf * (1.0f - S0f) * vik + sf * Svk - Tvk) * INV_TK; // grad2 (pre-rotation)
            rv[t] = r1 + r2;
        }
        __syncthreads();

        if (t < 16) {
            const float* om = g_Om + (size_t)bn * 256 + t * 16;  // row t of Om_i
            float acc = 0.0f;
            #pragma unroll
            for (int cc = 0; cc < 16; ++cc) acc += om[cc] * rv[cc];
            float m  = mu[bn * 16 + t];
            float mp = mu_prior[bn * 16 + t];
            out[bn * 16 + t] = m - lr * (ALPHA * (m - mp) + acc);
        }
        __syncthreads();  // protect red/fin/rv reuse in next ii
    }
}

// ---------------------------------------------------------------------------
extern "C" void kernel_launch(void* const* d_in, const int* in_sizes, int n_in,
                              void* d_out, int out_size) {
    const float* mu       = (const float*)d_in[0];
    const float* beta     = (const float*)d_in[1];
    const float* mu_prior = (const float*)d_in[2];
    const float* phi      = (const float*)d_in[3];
    const float* gen      = (const float*)d_in[4];
    const float* lr       = (const float*)d_in[5];
    float* out = (float*)d_out;

    expm_v_kernel<<<BN, 256>>>(mu, phi, gen);
    vffn_main_kernel<<<BN / RPB, 256>>>(beta, mu, mu_prior, lr, out);
}

// round 3
// speedup vs baseline: 3.6218x; 3.6218x over previous
#include <cuda_runtime.h>
#include <cuda_bf16.h>

#define B_  8
#define H_  8
#define N_  512
#define K_  16
#define BN  (B_*N_)          // 4096
#define NN  (N_*N_)          // 262144
#define M_TAYLOR 24

__device__ float g_A[BN * 256];   // per-(b,n) algebra element A = phi . G, row-major 16x16
__device__ float g_V[BN * K_];    // v = exp(-A) mu

// ---------------------------------------------------------------------------
// Warp-collective: y = exp(A) x for a 16x16 A.
// Lane l owns row r = l&15 of A (Ar[16] registers, lanes 16-31 mirror lanes 0-15).
// x_own = component r of x. Returns component r of exp(A) x.
// Horner: y <- x + (A y)/k, k = M..1. y kept replicated in all lanes.
// ---------------------------------------------------------------------------
__device__ __forceinline__ float exp_apply(const float Ar[16], float x_own) {
    float x[16], y[16];
    #pragma unroll
    for (int c = 0; c < 16; ++c) {
        x[c] = __shfl_sync(0xffffffffu, x_own, c);
        y[c] = x[c];
    }
    float y_own = x_own;
    #pragma unroll
    for (int k = M_TAYLOR; k >= 1; --k) {
        float z0 = 0.0f, z1 = 0.0f;
        #pragma unroll
        for (int c = 0; c < 16; c += 2) {
            z0 += Ar[c]     * y[c];
            z1 += Ar[c + 1] * y[c + 1];
        }
        float zk = (z0 + z1) * (1.0f / (float)k);
        y_own = x_own + zk;
        #pragma unroll
        for (int c = 0; c < 16; ++c)
            y[c] = x[c] + __shfl_sync(0xffffffffu, zk, c);
    }
    return y_own;
}

// ---------------------------------------------------------------------------
// Kernel 1: per (b,n): build A = sum_g phi_g G_g (store), v = exp(-A) mu (store).
// One warp per row; 8 warps per block.
// ---------------------------------------------------------------------------
__global__ __launch_bounds__(256)
void prep_kernel(const float* __restrict__ mu,
                 const float* __restrict__ phi,
                 const float* __restrict__ gen) {
    int w = threadIdx.x >> 5, lane = threadIdx.x & 31, r = lane & 15;
    int bn = blockIdx.x * 8 + w;

    float p0 = phi[bn * 3 + 0], p1 = phi[bn * 3 + 1], p2 = phi[bn * 3 + 2];

    float Ar[16];
    const float4* g4 = (const float4*)gen;
    #pragma unroll
    for (int q = 0; q < 4; ++q) {
        float4 a = g4[(0 * 256 + r * 16) / 4 + q];
        float4 b = g4[(1 * 256 + r * 16) / 4 + q];
        float4 c = g4[(2 * 256 + r * 16) / 4 + q];
        Ar[4 * q + 0] = p0 * a.x + p1 * b.x + p2 * c.x;
        Ar[4 * q + 1] = p0 * a.y + p1 * b.y + p2 * c.y;
        Ar[4 * q + 2] = p0 * a.z + p1 * b.z + p2 * c.z;
        Ar[4 * q + 3] = p0 * a.w + p1 * b.w + p2 * c.w;
    }
    if (lane < 16) {
        float4* A4 = (float4*)(g_A + (size_t)bn * 256 + r * 16);
        #pragma unroll
        for (int q = 0; q < 4; ++q)
            A4[q] = make_float4(Ar[4*q], Ar[4*q+1], Ar[4*q+2], Ar[4*q+3]);
    }

    float nAr[16];
    #pragma unroll
    for (int c = 0; c < 16; ++c) nAr[c] = -Ar[c];

    float x_own = mu[bn * 16 + r];
    float v = exp_apply(nAr, x_own);
    if (lane < 16) g_V[bn * 16 + lane] = v;
}

// ---------------------------------------------------------------------------
// Kernel 2: warp-per-row main pass. Block = 8 warps = 8 rows of one batch.
// V[b] cached in smem stride-20 (conflict-free float4 LDS). Per-warp butterfly
// reduction, then fused exp(A) action epilogue + mu update. No __syncthreads
// inside the j-loop.
// ---------------------------------------------------------------------------
__global__ __launch_bounds__(256, 2)
void vffn_main_kernel(const float* __restrict__ beta,
                      const float* __restrict__ mu,
                      const float* __restrict__ mu_prior,
                      const float* __restrict__ lr_ptr,
                      float* __restrict__ out) {
    __shared__ float Vs[N_ * 20];
    __shared__ float qs[N_];
    __shared__ float scratch[8][16];

    int t = threadIdx.x, lane = t & 31, w = t >> 5, r = lane & 15;
    int b = blockIdx.x >> 6;                 // 64 blocks per batch
    int i = ((blockIdx.x & 63) << 3) + w;    // this warp's row
    int bn = b * N_ + i;
    float lr = *lr_ptr;

    // Stage V[b] into padded smem (stride 20 floats; float4-aligned)
    const float4* V4 = (const float4*)(g_V + (size_t)b * N_ * K_);
    for (int idx = t; idx < N_ * 4; idx += 256) {
        int j = idx >> 2, q = idx & 3;
        ((float4*)(Vs + j * 20))[q] = V4[j * 4 + q];
    }
    __syncthreads();
    for (int j = t; j < N_; j += 256) {
        float q = 0.0f;
        #pragma unroll
        for (int k = 0; k < 16; ++k) { float v = Vs[j * 20 + k]; q += v * v; }
        qs[j] = q;
    }
    __syncthreads();

    // vi (broadcast LDS) and qi
    float vi[16];
    #pragma unroll
    for (int q = 0; q < 4; ++q) {
        float4 v4 = ((const float4*)(Vs + i * 20))[q];
        vi[4*q] = v4.x; vi[4*q+1] = v4.y; vi[4*q+2] = v4.z; vi[4*q+3] = v4.w;
    }
    float qi = qs[i];

    float S0 = 0.0f, sac = 0.0f;
    float Sv[16], Tv[16];
    #pragma unroll
    for (int k = 0; k < 16; ++k) { Sv[k] = 0.0f; Tv[k] = 0.0f; }

    const float* bb = beta + (size_t)b * H_ * NN + (size_t)i * N_;

    #pragma unroll 4
    for (int jj = 0; jj < 16; ++jj) {
        int j = lane + jj * 32;
        // 8 head loads (batched for MLP)
        float b0 = bb[0*NN + j], b1 = bb[1*NN + j], b2 = bb[2*NN + j], b3 = bb[3*NN + j];
        float b4 = bb[4*NN + j], b5 = bb[5*NN + j], b6 = bb[6*NN + j], b7 = bb[7*NN + j];
        float cb = (((b0 + b1) + (b2 + b3)) + ((b4 + b5) + (b6 + b7))) * 0.125f;

        float vj[16];
        #pragma unroll
        for (int q = 0; q < 4; ++q) {
            float4 u = ((const float4*)(Vs + j * 20))[q];
            vj[4*q] = u.x; vj[4*q+1] = u.y; vj[4*q+2] = u.z; vj[4*q+3] = u.w;
        }
        float d0 = 0.0f, d1 = 0.0f;
        #pragma unroll
        for (int k = 0; k < 16; k += 2) { d0 += vi[k]*vj[k]; d1 += vi[k+1]*vj[k+1]; }
        float kl  = 0.5f * (qi + qs[j]) - (d0 + d1);   // / TAU = 1
        float wgt = cb * kl;
        S0  += cb;
        sac += wgt;
        #pragma unroll
        for (int k = 0; k < 16; ++k) {
            Sv[k] += cb  * vj[k];
            Tv[k] += wgt * vj[k];
        }
    }

    // Butterfly all-reduce of the 34 partials across the warp
    #pragma unroll
    for (int off = 16; off > 0; off >>= 1) {
        S0  += __shfl_xor_sync(0xffffffffu, S0,  off);
        sac += __shfl_xor_sync(0xffffffffu, sac, off);
        #pragma unroll
        for (int k = 0; k < 16; ++k) {
            Sv[k] += __shfl_xor_sync(0xffffffffu, Sv[k], off);
            Tv[k] += __shfl_xor_sync(0xffffffffu, Tv[k], off);
        }
    }

    // rv (pre-rotation gradient), replicated in all lanes
    float rv[16];
    #pragma unroll
    for (int k = 0; k < 16; ++k) {
        float r1 = S0 * vi[k] - Sv[k];                                // grad1 (tau=1)
        float r2 = sac * (1.0f - S0) * vi[k] + sac * Sv[k] - Tv[k];   // grad2 (tau*kappa=1)
        rv[k] = r1 + r2;
    }
    // Extract component r into rv_own via per-warp smem staging
    if (lane == 0) {
        #pragma unroll
        for (int c = 0; c < 16; ++c) scratch[w][c] = rv[c];
    }
    __syncwarp();
    float rv_own = scratch[w][r];

    // Load A row r, apply rotation grad = exp(A) rv
    float Ar[16];
    const float4* A4 = (const float4*)(g_A + (size_t)bn * 256 + r * 16);
    #pragma unroll
    for (int q = 0; q < 4; ++q) {
        float4 a = A4[q];
        Ar[4*q] = a.x; Ar[4*q+1] = a.y; Ar[4*q+2] = a.z; Ar[4*q+3] = a.w;
    }
    float grad = exp_apply(Ar, rv_own);

    if (lane < 16) {
        float m  = mu[bn * 16 + lane];
        float mp = mu_prior[bn * 16 + lane];
        out[bn * 16 + lane] = m - lr * (0.001f * (m - mp) + grad);
    }
}

// ---------------------------------------------------------------------------
extern "C" void kernel_launch(void* const* d_in, const int* in_sizes, int n_in,
                              void* d_out, int out_size) {
    const float* mu       = (const float*)d_in[0];
    const float* beta     = (const float*)d_in[1];
    const float* mu_prior = (const float*)d_in[2];
    const float* phi      = (const float*)d_in[3];
    const float* gen      = (const float*)d_in[4];
    const float* lr       = (const float*)d_in[5];
    float* out = (float*)d_out;

    prep_kernel<<<BN / 8, 256>>>(mu, phi, gen);
    vffn_main_kernel<<<BN / 8, 256>>>(beta, mu, mu_prior, lr, out);
}